// round 8
// baseline (speedup 1.0000x reference)
#include <cuda_runtime.h>
#include <cuda_fp16.h>
#include <cstdint>

// Problem constants
#define B_  32
#define T_  1000
#define I_  3
#define R_  2048
#define O_  3

#define CAP     160          // per-row nnz capacity (padded to mult of 16)
#define GRID    128          // persistent CTAs (all co-resident)
#define RPC     16           // rows per CTA
#define NTHR    512          // 16 warps, warp-per-row
#define XBLK    32           // x staging window (steps)

// ---------------- device scratch ----------------
__device__ __half            g_state[2][R_ * B_];     // fp16 state, [r][b], 64B/row
__device__ float             g_final[R_ * B_];        // fp32 final state for outproj
__device__ unsigned          g_cols[R_][CAP];         // col * 8 (uint2-word offset of fp16 row)
__device__ float             g_vals[R_][CAP];
__device__ int               g_cnt[R_];               // padded to multiple of 16, >=16
__device__ unsigned          g_flag[GRID * 32];       // one 128B line per CTA (arrivals)
__device__ unsigned          g_go[32];                // single go word (own line)

// ---------------- helpers ----------------
__device__ __forceinline__ unsigned ld_acq(const unsigned* p) {
    unsigned v;
    asm volatile("ld.acquire.gpu.u32 %0, [%1];" : "=r"(v) : "l"(p) : "memory");
    return v;
}
__device__ __forceinline__ void st_rel(unsigned* p, unsigned v) {
    asm volatile("st.release.gpu.u32 [%0], %1;" :: "l"(p), "r"(v) : "memory");
}
__device__ __forceinline__ float tanh_fast(float x) {
    float y;
    asm("tanh.approx.f32 %0, %1;" : "=f"(y) : "f"(x));
    return y;
}

// ---------------- P1: sparse compaction + init ----------------
__global__ void prep_kernel(const float* __restrict__ W) {
    int r = blockIdx.x;
    int lane = threadIdx.x;
    const float* row = W + (size_t)r * R_;

    int base = 0;
    for (int c0 = 0; c0 < R_; c0 += 32) {
        float v = row[c0 + lane];
        unsigned m = __ballot_sync(0xffffffffu, v != 0.0f);
        if (v != 0.0f) {
            int off = __popc(m & ((1u << lane) - 1u));
            int p = base + off;
            if (p < CAP) {
                g_cols[r][p] = (unsigned)(c0 + lane) * 8u;   // uint2 units per fp16 row
                g_vals[r][p] = v;
            }
        }
        base += __popc(m);
    }
    if (base > CAP) base = CAP;
    int padded = (base + 15) & ~15;
    if (padded < 16) padded = 16;
    if (padded > CAP) padded = CAP;
    for (int p = base + lane; p < padded; p += 32) {
        g_cols[r][p] = ((unsigned)(r * 7 + p * 13) & (R_ - 1)) * 8u;
        g_vals[r][p] = 0.0f;
    }
    if (lane == 0) g_cnt[r] = padded;

    // reset per-launch mutable state (graph replay safe)
    g_state[0][r * B_ + lane] = __float2half(0.0f);
    if (r < GRID && lane == 0) g_flag[r << 5] = 0u;
    if (r == 0 && lane == 0) g_go[0] = 0u;
}

// ---------------- P2: persistent recurrence ----------------
__global__ void __launch_bounds__(NTHR, 1)
esn_kernel(const float* __restrict__ x,        // [B,T,I]
           const float* __restrict__ win,      // [R,I]
           const float* __restrict__ noise,    // [B,R]
           float* __restrict__ states_out) {   // [B,T,R]
    __shared__ uint2 snnz[RPC][CAP];           // (col*8, val bits)  20 KB
    __shared__ float tile[RPC][B_ + 1];        // staged fp32 outputs for transpose
    __shared__ float xs[XBLK][B_][4];          // 32-step x window, 16 KB

    const int tid  = threadIdx.x;
    const int w    = tid >> 5;                 // warp = local row
    const int lane = tid & 31;
    const int q    = lane >> 3;                // quarter: handles nnz 4j+q
    const int l    = lane & 7;                 // batch quad: batches 4l..4l+3
    const int rbase = blockIdx.x * RPC;
    const int r = rbase + w;

    // preload sparse row into SMEM (reused for all 1000 steps)
    const int cnt = g_cnt[r];
    for (int k = lane; k < cnt; k += 32)
        snnz[w][k] = make_uint2(g_cols[r][k], __float_as_uint(g_vals[r][k]));

    // per-thread constants (4 batches per lane)
    float nz[4];
    #pragma unroll
    for (int i = 0; i < 4; i++) nz[i] = noise[(size_t)(4 * l + i) * R_ + r];
    const float w0 = win[r * 3 + 0];
    const float w1 = win[r * 3 + 1];
    const float w2 = win[r * 3 + 2];

    // x window refill: 3072 floats, 6 per thread
    auto refill_x = [&](int t0) {
        for (int g = tid; g < XBLK * B_ * I_; g += NTHR) {
            int b = g / (XBLK * I_);
            int rem = g - b * (XBLK * I_);
            int tp = rem / I_, i = rem - tp * I_;
            float v = (t0 + tp < T_) ? __ldg(&x[(size_t)b * (T_ * I_) + (t0 + tp) * I_ + i])
                                     : 0.0f;
            xs[tp][b][i] = v;
        }
    };
    refill_x(0);
    __syncthreads();

    const int nj = cnt >> 2;                   // nnz per quarter (multiple of 4)

    for (int t = 0; t < T_; t++) {
        const uint2* cur = (const uint2*)&g_state[t & 1][0];
        uint2* nxt       = (uint2*)&g_state[(t + 1) & 1][0];
        const int tw = t & (XBLK - 1);

        // input term for this lane's 4 batches (computed redundantly per quarter)
        float acc[4];
        #pragma unroll
        for (int i = 0; i < 4; i++) {
            int b = 4 * l + i;
            float ax = fmaf(w0, xs[tw][b][0],
                       fmaf(w1, xs[tw][b][1],
                       fmaf(w2, xs[tw][b][2], nz[i])));
            acc[i] = (q == 0) ? ax : 0.0f;
        }

        // ---- software-pipelined gather: 4 LDG.64/chunk, each LDG covers 4 nnz ----
        uint2 sA[4]; float vA[4];
        uint2 sB[4]; float vB[4];

        auto load4 = [&](uint2* s, float* v, int jbase) {
            #pragma unroll
            for (int jj = 0; jj < 4; jj++) {
                uint2 e = snnz[w][((jbase + jj) << 2) + q];
                v[jj] = __uint_as_float(e.y);
                s[jj] = __ldcg(cur + e.x + l);     // 8B = 4 fp16 batches
            }
        };
        auto consume4 = [&](const uint2* s, const float* v) {
            #pragma unroll
            for (int jj = 0; jj < 4; jj++) {
                float2 f0 = __half22float2(*(const __half2*)&s[jj].x);
                float2 f1 = __half22float2(*(const __half2*)&s[jj].y);
                acc[0] = fmaf(v[jj], f0.x, acc[0]);
                acc[1] = fmaf(v[jj], f0.y, acc[1]);
                acc[2] = fmaf(v[jj], f1.x, acc[2]);
                acc[3] = fmaf(v[jj], f1.y, acc[3]);
            }
        };

        load4(sA, vA, 0);
        for (int j = 4; j < nj; j += 8) {
            load4(sB, vB, j);
            consume4(sA, vA);
            if (j + 4 < nj) load4(sA, vA, j + 4);
            consume4(sB, vB);
        }
        if ((nj >> 2) & 1) consume4(sA, vA);

        // merge quarters: lanes l, l+8, l+16, l+24 hold partials for same batches
        #pragma unroll
        for (int i = 0; i < 4; i++) {
            acc[i] += __shfl_xor_sync(0xffffffffu, acc[i], 8);
            acc[i] += __shfl_xor_sync(0xffffffffu, acc[i], 16);
            acc[i] = tanh_fast(acc[i]);
        }

        if (q == 0) {
            __half2 h0 = __floats2half2_rn(acc[0], acc[1]);
            __half2 h1 = __floats2half2_rn(acc[2], acc[3]);
            uint2 pk = make_uint2(*(unsigned*)&h0, *(unsigned*)&h1);
            nxt[r * 8 + l] = pk;                  // 64B coalesced state store
            tile[w][4 * l + 0] = acc[0];
            tile[w][4 * l + 1] = acc[1];
            tile[w][4 * l + 2] = acc[2];
            tile[w][4 * l + 3] = acc[3];
            if (t == T_ - 1) {
                #pragma unroll
                for (int i = 0; i < 4; i++)
                    g_final[r * B_ + 4 * l + i] = acc[i];
            }
        }
        __syncthreads();                          // all state/tile stores done

        // arrival: release orders all prior stores (cumulative via bar.sync)
        if (tid == 0) st_rel(&g_flag[blockIdx.x << 5], (unsigned)(t + 1));

        // ---- off-critical-path work while barrier resolves ----
        {   // transposed states write: half-warp writes 64B contiguous per batch
            int b  = w + ((lane >> 4) << 4);      // w or w+16
            int rr = lane & 15;
            __stcs(&states_out[(size_t)b * (T_ * R_) + (size_t)t * R_ + rbase + rr],
                   tile[rr][b]);
        }
        if (((t + 1) & (XBLK - 1)) == 0 && t + 1 < T_)
            refill_x(t + 1);                      // next 32-step x window

        // ---- master/go barrier ----
        if (blockIdx.x == 0) {
            if (tid < GRID) {
                while (ld_acq(&g_flag[tid << 5]) < (unsigned)(t + 1)) { }
            }
            __syncthreads();
            if (tid == 0) st_rel(&g_go[0], (unsigned)(t + 1));
        } else {
            if (tid == 0) {
                while (ld_acq(&g_go[0]) < (unsigned)(t + 1)) { }
            }
        }
        __syncthreads();
    }
}

// ---------------- P3: output projection ----------------
__global__ void outproj_kernel(const float* __restrict__ wout,  // [O,R]
                               float* __restrict__ out) {       // [B*O]
    __shared__ float red[256];
    int pair = blockIdx.x;            // 0..95
    int b = pair / O_, o = pair - b * O_;

    float sum = 0.0f;
    for (int r = threadIdx.x; r < R_; r += blockDim.x)
        sum += g_final[r * B_ + b] * wout[o * R_ + r];

    red[threadIdx.x] = sum;
    __syncthreads();
    for (int s = 128; s > 0; s >>= 1) {
        if (threadIdx.x < s) red[threadIdx.x] += red[threadIdx.x + s];
        __syncthreads();
    }
    if (threadIdx.x == 0) out[b * O_ + o] = red[0];
}

// ---------------- launch ----------------
extern "C" void kernel_launch(void* const* d_in, const int* in_sizes, int n_in,
                              void* d_out, int out_size) {
    (void)in_sizes; (void)n_in; (void)out_size;
    const float* x     = (const float*)d_in[0];   // [B,T,I]
    const float* win   = (const float*)d_in[1];   // [R,I]
    const float* wres  = (const float*)d_in[2];   // [R,R]
    const float* wout  = (const float*)d_in[3];   // [O,R]
    const float* noise = (const float*)d_in[4];   // [B,R]
    float* out = (float*)d_out;                   // [B*O] then [B,T,R]

    prep_kernel<<<R_, 32>>>(wres);
    esn_kernel<<<GRID, NTHR>>>(x, win, noise, out + B_ * O_);
    outproj_kernel<<<B_ * O_, 256>>>(wout, out);
}

// round 9
// speedup vs baseline: 1.3702x; 1.3702x over previous
#include <cuda_runtime.h>
#include <cuda_fp16.h>
#include <cstdint>

// Problem constants
#define B_  32
#define T_  1000
#define I_  3
#define R_  2048
#define O_  3

#define CAP     160          // per-row nnz capacity (padded to mult of 16)
#define GRID    64           // persistent CTAs (1 per SM, all co-resident)
#define RPC     32           // rows per CTA
#define NTHR    1024         // 32 warps, warp-per-row
#define XBLK    32           // x staging window (steps)

// ---------------- device scratch ----------------
__device__ __half            g_state[2][R_ * B_];     // fp16 state, [r][b], 64B/row
__device__ float             g_final[R_ * B_];        // fp32 final state for outproj
__device__ unsigned          g_cols[R_][CAP];         // col * 8 (uint2 offset of fp16 row)
__device__ float             g_vals[R_][CAP];
__device__ int               g_cnt[R_];               // padded to multiple of 16, >=16
__device__ unsigned          g_flag[GRID * 32];       // one 128B line per CTA (arrivals)

// ---------------- helpers ----------------
__device__ __forceinline__ unsigned ld_acq(const unsigned* p) {
    unsigned v;
    asm volatile("ld.acquire.gpu.u32 %0, [%1];" : "=r"(v) : "l"(p) : "memory");
    return v;
}
__device__ __forceinline__ void st_rel(unsigned* p, unsigned v) {
    asm volatile("st.release.gpu.u32 [%0], %1;" :: "l"(p), "r"(v) : "memory");
}
__device__ __forceinline__ float tanh_fast(float x) {
    float y;
    asm("tanh.approx.f32 %0, %1;" : "=f"(y) : "f"(x));
    return y;
}

// ---------------- P1: sparse compaction + init ----------------
__global__ void prep_kernel(const float* __restrict__ W) {
    int r = blockIdx.x;
    int lane = threadIdx.x;
    const float* row = W + (size_t)r * R_;

    int base = 0;
    for (int c0 = 0; c0 < R_; c0 += 32) {
        float v = row[c0 + lane];
        unsigned m = __ballot_sync(0xffffffffu, v != 0.0f);
        if (v != 0.0f) {
            int off = __popc(m & ((1u << lane) - 1u));
            int p = base + off;
            if (p < CAP) {
                g_cols[r][p] = (unsigned)(c0 + lane) * 8u;   // uint2 units per fp16 row
                g_vals[r][p] = v;
            }
        }
        base += __popc(m);
    }
    if (base > CAP) base = CAP;
    int padded = (base + 15) & ~15;
    if (padded < 16) padded = 16;
    if (padded > CAP) padded = CAP;
    for (int p = base + lane; p < padded; p += 32) {
        g_cols[r][p] = ((unsigned)(r * 7 + p * 13) & (R_ - 1)) * 8u;
        g_vals[r][p] = 0.0f;
    }
    if (lane == 0) g_cnt[r] = padded;

    // reset per-launch mutable state (graph replay safe)
    g_state[0][r * B_ + lane] = __float2half(0.0f);
    if (r < GRID && lane == 0) g_flag[r << 5] = 0u;
}

// ---------------- P2: persistent recurrence ----------------
__global__ void __launch_bounds__(NTHR, 1)
esn_kernel(const float* __restrict__ x,        // [B,T,I]
           const float* __restrict__ win,      // [R,I]
           const float* __restrict__ noise,    // [B,R]
           float* __restrict__ states_out) {   // [B,T,R]
    __shared__ uint2 snnz[RPC][CAP];           // (col*8, val bits)  40 KB
    __shared__ float tile[RPC][B_ + 1];        // staged fp32 outputs, 4.2 KB
    __shared__ float xs[XBLK][B_][4];          // 32-step x window, 16 KB

    const int tid  = threadIdx.x;
    const int w    = tid >> 5;                 // warp = local row (0..31)
    const int lane = tid & 31;
    const int q    = lane >> 3;                // quarter: handles nnz 4j+q
    const int l    = lane & 7;                 // batch quad: batches 4l..4l+3
    const int rbase = blockIdx.x * RPC;
    const int r = rbase + w;

    // preload sparse row into SMEM (reused for all 1000 steps)
    const int cnt = g_cnt[r];
    for (int k = lane; k < cnt; k += 32)
        snnz[w][k] = make_uint2(g_cols[r][k], __float_as_uint(g_vals[r][k]));

    // per-thread constants (4 batches per lane)
    float nz[4];
    #pragma unroll
    for (int i = 0; i < 4; i++) nz[i] = noise[(size_t)(4 * l + i) * R_ + r];
    const float w0 = win[r * 3 + 0];
    const float w1 = win[r * 3 + 1];
    const float w2 = win[r * 3 + 2];

    // x window refill: 3072 floats, 3 per thread
    auto refill_x = [&](int t0) {
        for (int g = tid; g < XBLK * B_ * I_; g += NTHR) {
            int b = g / (XBLK * I_);
            int rem = g - b * (XBLK * I_);
            int tp = rem / I_, i = rem - tp * I_;
            float v = (t0 + tp < T_) ? __ldg(&x[(size_t)b * (T_ * I_) + (t0 + tp) * I_ + i])
                                     : 0.0f;
            xs[tp][b][i] = v;
        }
    };
    refill_x(0);
    __syncthreads();

    const int nj = cnt >> 2;                   // nnz per quarter (multiple of 4)

    for (int t = 0; t < T_; t++) {
        const uint2* cur = (const uint2*)&g_state[t & 1][0];
        uint2* nxt       = (uint2*)&g_state[(t + 1) & 1][0];
        const int tw = t & (XBLK - 1);

        // input term for this lane's 4 batches (redundant per quarter; q!=0 zeroed)
        float acc[4];
        #pragma unroll
        for (int i = 0; i < 4; i++) {
            int b = 4 * l + i;
            float ax = fmaf(w0, xs[tw][b][0],
                       fmaf(w1, xs[tw][b][1],
                       fmaf(w2, xs[tw][b][2], nz[i])));
            acc[i] = (q == 0) ? ax : 0.0f;
        }

        // ---- software-pipelined gather: 4 LDG.64/chunk, each LDG covers 4 nnz ----
        uint2 sA[4]; float vA[4];
        uint2 sB[4]; float vB[4];

        auto load4 = [&](uint2* s, float* v, int jbase) {
            #pragma unroll
            for (int jj = 0; jj < 4; jj++) {
                uint2 e = snnz[w][((jbase + jj) << 2) + q];
                v[jj] = __uint_as_float(e.y);
                s[jj] = __ldcg(cur + e.x + l);     // 8B = 4 fp16 batches
            }
        };
        auto consume4 = [&](const uint2* s, const float* v) {
            #pragma unroll
            for (int jj = 0; jj < 4; jj++) {
                float2 f0 = __half22float2(*(const __half2*)&s[jj].x);
                float2 f1 = __half22float2(*(const __half2*)&s[jj].y);
                acc[0] = fmaf(v[jj], f0.x, acc[0]);
                acc[1] = fmaf(v[jj], f0.y, acc[1]);
                acc[2] = fmaf(v[jj], f1.x, acc[2]);
                acc[3] = fmaf(v[jj], f1.y, acc[3]);
            }
        };

        load4(sA, vA, 0);
        for (int j = 4; j < nj; j += 8) {
            load4(sB, vB, j);
            consume4(sA, vA);
            if (j + 4 < nj) load4(sA, vA, j + 4);
            consume4(sB, vB);
        }
        if ((nj >> 2) & 1) consume4(sA, vA);

        // merge quarters: lanes l, l+8, l+16, l+24 hold partials for same batches
        #pragma unroll
        for (int i = 0; i < 4; i++) {
            acc[i] += __shfl_xor_sync(0xffffffffu, acc[i], 8);
            acc[i] += __shfl_xor_sync(0xffffffffu, acc[i], 16);
            acc[i] = tanh_fast(acc[i]);
        }

        if (q == 0) {
            __half2 h0 = __floats2half2_rn(acc[0], acc[1]);
            __half2 h1 = __floats2half2_rn(acc[2], acc[3]);
            uint2 pk = make_uint2(*(unsigned*)&h0, *(unsigned*)&h1);
            nxt[r * 8 + l] = pk;                  // 64B coalesced state store
            tile[w][4 * l + 0] = acc[0];
            tile[w][4 * l + 1] = acc[1];
            tile[w][4 * l + 2] = acc[2];
            tile[w][4 * l + 3] = acc[3];
            if (t == T_ - 1) {
                #pragma unroll
                for (int i = 0; i < 4; i++)
                    g_final[r * B_ + 4 * l + i] = acc[i];
            }
        }
        __syncthreads();                          // all state/tile stores done

        // arrival: release orders all prior stores (cumulative via bar.sync)
        if (tid == 0) st_rel(&g_flag[blockIdx.x << 5], (unsigned)(t + 1));

        // ---- off-critical-path work while barrier resolves ----
        {   // transposed states write: warp w = batch w, 128B contiguous line
            __stcs(&states_out[(size_t)w * (T_ * R_) + (size_t)t * R_ + rbase + lane],
                   tile[lane][w]);
        }
        if (((t + 1) & (XBLK - 1)) == 0 && t + 1 < T_)
            refill_x(t + 1);                      // next 32-step x window

        // ---- flat barrier: 64 threads poll 64 distinct flag lines ----
        if (tid < GRID) {
            while (ld_acq(&g_flag[tid << 5]) < (unsigned)(t + 1)) { }
        }
        __syncthreads();
    }
}

// ---------------- P3: output projection ----------------
__global__ void outproj_kernel(const float* __restrict__ wout,  // [O,R]
                               float* __restrict__ out) {       // [B*O]
    __shared__ float red[256];
    int pair = blockIdx.x;            // 0..95
    int b = pair / O_, o = pair - b * O_;

    float sum = 0.0f;
    for (int r = threadIdx.x; r < R_; r += blockDim.x)
        sum += g_final[r * B_ + b] * wout[o * R_ + r];

    red[threadIdx.x] = sum;
    __syncthreads();
    for (int s = 128; s > 0; s >>= 1) {
        if (threadIdx.x < s) red[threadIdx.x] += red[threadIdx.x + s];
        __syncthreads();
    }
    if (threadIdx.x == 0) out[b * O_ + o] = red[0];
}

// ---------------- launch ----------------
extern "C" void kernel_launch(void* const* d_in, const int* in_sizes, int n_in,
                              void* d_out, int out_size) {
    (void)in_sizes; (void)n_in; (void)out_size;
    const float* x     = (const float*)d_in[0];   // [B,T,I]
    const float* win   = (const float*)d_in[1];   // [R,I]
    const float* wres  = (const float*)d_in[2];   // [R,R]
    const float* wout  = (const float*)d_in[3];   // [O,R]
    const float* noise = (const float*)d_in[4];   // [B,R]
    float* out = (float*)d_out;                   // [B*O] then [B,T,R]

    prep_kernel<<<R_, 32>>>(wres);
    esn_kernel<<<GRID, NTHR>>>(x, win, noise, out + B_ * O_);
    outproj_kernel<<<B_ * O_, 256>>>(wout, out);
}

// round 11
// speedup vs baseline: 1.5740x; 1.1487x over previous
#include <cuda_runtime.h>
#include <cuda_fp16.h>
#include <cstdint>

// Problem constants
#define B_  32
#define T_  1000
#define I_  3
#define R_  2048
#define O_  3

#define CAP     160          // per-row nnz capacity (padded to mult of 16)
#define GRID    128          // persistent CTAs, 64 clusters of 2 (perfect packing)
#define CLS     2
#define RPC     16           // rows per CTA
#define NTHR    512          // 16 warps, warp-per-row
#define XBLK    32           // x staging window (steps)

#define SLICE_BYTES 65536    // 1024 state rows x 64B, per-rank multicast slice
#define STATE_BYTES 131072   // full state, fp16 [2048][32]

// dynamic SMEM layout (bytes)
#define SM_STATE 0
#define SM_SNNZ  (SM_STATE + STATE_BYTES)                 // 16*160*8 = 20480
#define SM_XS    (SM_SNNZ + RPC * CAP * 8)                // 32*32*4*4 = 16384
#define SM_TILE  (SM_XS + XBLK * B_ * 4 * 4)              // 16*33*4 = 2112
#define SM_MBAR  (SM_TILE + RPC * (B_ + 1) * 4)
#define SM_TOTAL (SM_MBAR + 32)

// ---------------- device scratch ----------------
__device__ __half    g_state16[2][R_ * B_];   // fp16 state, [r][b], 64B/row
__device__ float     g_final[R_ * B_];        // fp32 final state for outproj
__device__ unsigned  g_cols[R_][CAP];         // col * 64 (byte offset of state row)
__device__ float     g_vals[R_][CAP];
__device__ int       g_cnt[R_];               // padded to multiple of 16, >=16
__device__ unsigned  g_flag[GRID * 32];       // one 128B line per CTA

// ---------------- helpers ----------------
__device__ __forceinline__ unsigned ld_acq(const unsigned* p) {
    unsigned v;
    asm volatile("ld.acquire.gpu.u32 %0, [%1];" : "=r"(v) : "l"(p) : "memory");
    return v;
}
__device__ __forceinline__ void st_rel(unsigned* p, unsigned v) {
    asm volatile("st.release.gpu.u32 [%0], %1;" :: "l"(p), "r"(v) : "memory");
}
__device__ __forceinline__ float tanh_fast(float x) {
    float y;
    asm("tanh.approx.f32 %0, %1;" : "=f"(y) : "f"(x));
    return y;
}
__device__ __forceinline__ unsigned smem_u32(const void* p) {
    unsigned a;
    asm("{ .reg .u64 t; cvta.to.shared.u64 t, %1; cvt.u32.u64 %0, t; }" : "=r"(a) : "l"(p));
    return a;
}
__device__ __forceinline__ unsigned ctarank() {
    unsigned r;
    asm("mov.u32 %0, %%cluster_ctarank;" : "=r"(r));
    return r;
}
__device__ __forceinline__ void mbar_init(unsigned a, unsigned cnt) {
    asm volatile("mbarrier.init.shared.b64 [%0], %1;" :: "r"(a), "r"(cnt) : "memory");
}
__device__ __forceinline__ void mbar_expect(unsigned a, unsigned bytes) {
    asm volatile("mbarrier.arrive.expect_tx.shared.b64 _, [%0], %1;" :: "r"(a), "r"(bytes) : "memory");
}
__device__ __forceinline__ void mbar_wait(unsigned a, unsigned par) {
    asm volatile(
        "{\n\t.reg .pred P;\n"
        "LW%=:\n\t"
        "mbarrier.try_wait.parity.acquire.cta.shared::cta.b64 P, [%0], %1, 0x989680;\n\t"
        "@P bra LD%=;\n\t"
        "bra LW%=;\n"
        "LD%=:\n\t}"
        :: "r"(a), "r"(par) : "memory");
}
__device__ __forceinline__ void bulk_mcast(unsigned dst, const void* src, unsigned bytes,
                                           unsigned mbar, unsigned short mask) {
    asm volatile(
        "cp.async.bulk.shared::cluster.global.mbarrier::complete_tx::bytes.multicast::cluster"
        " [%0], [%1], %2, [%3], %4;"
        :: "r"(dst), "l"(src), "r"(bytes), "r"(mbar), "h"(mask) : "memory");
}
__device__ __forceinline__ void cluster_sync() {
    asm volatile("barrier.cluster.arrive.aligned;" ::: "memory");
    asm volatile("barrier.cluster.wait.aligned;" ::: "memory");
}

// ---------------- P1: sparse compaction + init ----------------
__global__ void prep_kernel(const float* __restrict__ W) {
    int r = blockIdx.x;
    int lane = threadIdx.x;
    const float* row = W + (size_t)r * R_;

    int base = 0;
    for (int c0 = 0; c0 < R_; c0 += 32) {
        float v = row[c0 + lane];
        unsigned m = __ballot_sync(0xffffffffu, v != 0.0f);
        if (v != 0.0f) {
            int off = __popc(m & ((1u << lane) - 1u));
            int p = base + off;
            if (p < CAP) {
                g_cols[r][p] = (unsigned)(c0 + lane) * 64u;   // byte offset of state row
                g_vals[r][p] = v;
            }
        }
        base += __popc(m);
    }
    if (base > CAP) base = CAP;
    int padded = (base + 15) & ~15;
    if (padded < 16) padded = 16;
    if (padded > CAP) padded = CAP;
    for (int p = base + lane; p < padded; p += 32) {
        g_cols[r][p] = ((unsigned)(r * 7 + p * 13) & (R_ - 1)) * 64u;
        g_vals[r][p] = 0.0f;
    }
    if (lane == 0) g_cnt[r] = padded;

    // reset per-launch mutable state (graph replay safe)
    g_state16[0][r * B_ + lane] = __float2half(0.0f);
    if (r < GRID && lane == 0) g_flag[r << 5] = 0u;
}

// ---------------- P2: persistent recurrence, state in SMEM via multicast ----
__global__ void __launch_bounds__(NTHR, 1) __cluster_dims__(CLS, 1, 1)
esn_kernel(const float* __restrict__ x,        // [B,T,I]
           const float* __restrict__ win,      // [R,I]
           const float* __restrict__ noise,    // [B,R]
           float* __restrict__ states_out) {   // [B,T,R]
    extern __shared__ char dsm[];
    char*  sst  = dsm + SM_STATE;                       // fp16 state [2048][32]
    uint2* snz  = (uint2*)(dsm + SM_SNNZ);              // [w*CAP + k]
    float* xs   = (float*)(dsm + SM_XS);                // [(tw*B_+b)*4 + i]
    float* tile = (float*)(dsm + SM_TILE);              // [rr*(B_+1) + b]
    const unsigned mb = smem_u32(dsm + SM_MBAR);
    const unsigned sst_u = smem_u32(sst);

    const int tid  = threadIdx.x;
    const int w    = tid >> 5;                 // warp = local row
    const int lane = tid & 31;
    const int q    = lane >> 3;                // quarter: handles nnz 4j+q
    const int l    = lane & 7;                 // batch quad: batches 4l..4l+3
    const int rbase = blockIdx.x * RPC;
    const int r = rbase + w;
    const unsigned rk = ctarank();

    // preload sparse row into SMEM
    const int cnt = g_cnt[r];
    for (int k = lane; k < cnt; k += 32)
        snz[w * CAP + k] = make_uint2(g_cols[r][k], __float_as_uint(g_vals[r][k]));

    // per-thread constants (4 batches per lane)
    float nz[4];
    #pragma unroll
    for (int i = 0; i < 4; i++) nz[i] = noise[(size_t)(4 * l + i) * R_ + r];
    const float w0 = win[r * 3 + 0];
    const float w1 = win[r * 3 + 1];
    const float w2 = win[r * 3 + 2];

    auto refill_x = [&](int t0) {
        for (int g = tid; g < XBLK * B_ * I_; g += NTHR) {
            int b = g / (XBLK * I_);
            int rem = g - b * (XBLK * I_);
            int tp = rem / I_, i = rem - tp * I_;
            float v = (t0 + tp < T_) ? __ldg(&x[(size_t)b * (T_ * I_) + (t0 + tp) * I_ + i])
                                     : 0.0f;
            xs[((size_t)tp * B_ + b) * 4 + i] = v;
        }
    };
    refill_x(0);

    if (tid == 0) mbar_init(mb, 1);
    __syncthreads();
    cluster_sync();                            // both CTAs' mbars initialized
    if (tid == 0) {
        mbar_expect(mb, STATE_BYTES);          // phase 0: expect both 64KB slices
        asm volatile("fence.proxy.async;" ::: "memory");
        bulk_mcast(sst_u + rk * SLICE_BYTES,
                   (const char*)&g_state16[0][0] + rk * SLICE_BYTES,
                   SLICE_BYTES, mb, (unsigned short)0x3);
    }

    const int nj = cnt >> 2;                   // nnz per quarter (multiple of 4)

    for (int t = 0; t < T_; t++) {
        const int tw = t & (XBLK - 1);

        // input term for this lane's 4 batches (overlaps fill latency)
        float acc[4];
        #pragma unroll
        for (int i = 0; i < 4; i++) {
            int b = 4 * l + i;
            const float* xb = &xs[((size_t)tw * B_ + b) * 4];
            float ax = fmaf(w0, xb[0], fmaf(w1, xb[1], fmaf(w2, xb[2], nz[i])));
            acc[i] = (q == 0) ? ax : 0.0f;
        }

        // wait for fill t (phase t, parity t&1)
        mbar_wait(mb, (unsigned)(t & 1));

        // ---- LDS gather: quarter q handles nnz 4j+q, lane loads 8B (4 batches)
        #pragma unroll 4
        for (int j = 0; j < nj; j++) {
            uint2 e = snz[w * CAP + (j << 2) + q];
            uint2 sv = *reinterpret_cast<const uint2*>(sst + e.x + (l << 3));
            float vv = __uint_as_float(e.y);
            float2 f0 = __half22float2(*(const __half2*)&sv.x);
            float2 f1 = __half22float2(*(const __half2*)&sv.y);
            acc[0] = fmaf(vv, f0.x, acc[0]);
            acc[1] = fmaf(vv, f0.y, acc[1]);
            acc[2] = fmaf(vv, f1.x, acc[2]);
            acc[3] = fmaf(vv, f1.y, acc[3]);
        }

        // merge quarters (lanes l, l+8, l+16, l+24 share a batch quad)
        #pragma unroll
        for (int i = 0; i < 4; i++) {
            acc[i] += __shfl_xor_sync(0xffffffffu, acc[i], 8);
            acc[i] += __shfl_xor_sync(0xffffffffu, acc[i], 16);
            acc[i] = tanh_fast(acc[i]);
        }

        if (q == 0) {
            __half2 h0 = __floats2half2_rn(acc[0], acc[1]);
            __half2 h1 = __floats2half2_rn(acc[2], acc[3]);
            uint2 pk = make_uint2(*(unsigned*)&h0, *(unsigned*)&h1);
            ((uint2*)&g_state16[(t + 1) & 1][0])[r * 8 + l] = pk;   // 64B/row
            tile[w * (B_ + 1) + 4 * l + 0] = acc[0];
            tile[w * (B_ + 1) + 4 * l + 1] = acc[1];
            tile[w * (B_ + 1) + 4 * l + 2] = acc[2];
            tile[w * (B_ + 1) + 4 * l + 3] = acc[3];
            if (t == T_ - 1) {
                #pragma unroll
                for (int i = 0; i < 4; i++)
                    g_final[r * B_ + 4 * l + i] = acc[i];
            }
        }
        __syncthreads();                         // SMEM reads + all stores done

        if (t + 1 < T_) {
            // arm expect for fill t+1 BEFORE publishing arrival
            if (tid == 0) {
                mbar_expect(mb, STATE_BYTES);    // phase t+1
                st_rel(&g_flag[blockIdx.x << 5], (unsigned)(t + 1));
            }
        }

        // ---- off-critical-path: transposed states write, 64B per half-warp
        {
            int b  = w + ((lane >> 4) << 4);
            int rr = lane & 15;
            __stcs(&states_out[(size_t)b * (T_ * R_) + (size_t)t * R_ + rbase + rr],
                   tile[rr * (B_ + 1) + b]);
        }
        if (((t + 1) & (XBLK - 1)) == 0 && t + 1 < T_)
            refill_x(t + 1);

        if (t + 1 < T_) {
            // flat barrier: 128 threads poll 128 distinct flag lines
            if (tid < GRID) {
                while (ld_acq(&g_flag[tid << 5]) < (unsigned)(t + 1)) { }
            }
            __syncthreads();
            // all CTAs finished step t; fetch state[t+1] into SMEM
            if (tid == 0) {
                asm volatile("fence.proxy.async;" ::: "memory");
                bulk_mcast(sst_u + rk * SLICE_BYTES,
                           (const char*)&g_state16[(t + 1) & 1][0] + rk * SLICE_BYTES,
                           SLICE_BYTES, mb, (unsigned short)0x3);
            }
        }
    }

    cluster_sync();                              // no CTA exits with peer ops in flight
}

// ---------------- P3: output projection ----------------
__global__ void outproj_kernel(const float* __restrict__ wout,  // [O,R]
                               float* __restrict__ out) {       // [B*O]
    __shared__ float red[256];
    int pair = blockIdx.x;            // 0..95
    int b = pair / O_, o = pair - b * O_;

    float sum = 0.0f;
    for (int r = threadIdx.x; r < R_; r += blockDim.x)
        sum += g_final[r * B_ + b] * wout[o * R_ + r];

    red[threadIdx.x] = sum;
    __syncthreads();
    for (int s = 128; s > 0; s >>= 1) {
        if (threadIdx.x < s) red[threadIdx.x] += red[threadIdx.x + s];
        __syncthreads();
    }
    if (threadIdx.x == 0) out[b * O_ + o] = red[0];
}

// ---------------- launch ----------------
extern "C" void kernel_launch(void* const* d_in, const int* in_sizes, int n_in,
                              void* d_out, int out_size) {
    (void)in_sizes; (void)n_in; (void)out_size;
    const float* x     = (const float*)d_in[0];   // [B,T,I]
    const float* win   = (const float*)d_in[1];   // [R,I]
    const float* wres  = (const float*)d_in[2];   // [R,R]
    const float* wout  = (const float*)d_in[3];   // [O,R]
    const float* noise = (const float*)d_in[4];   // [B,R]
    float* out = (float*)d_out;                   // [B*O] then [B,T,R]

    cudaFuncSetAttribute(esn_kernel,
                         cudaFuncAttributeMaxDynamicSharedMemorySize, SM_TOTAL);

    prep_kernel<<<R_, 32>>>(wres);
    esn_kernel<<<GRID, NTHR, SM_TOTAL>>>(x, win, noise, out + B_ * O_);
    outproj_kernel<<<B_ * O_, 256>>>(wout, out);
}

// round 12
// speedup vs baseline: 1.7090x; 1.0858x over previous
#include <cuda_runtime.h>
#include <cuda_fp16.h>
#include <cstdint>

// Problem constants
#define B_  32
#define T_  1000
#define I_  3
#define R_  2048
#define O_  3

#define CAP     160          // per-row nnz capacity (padded to mult of 16)
#define GRID    128          // persistent CTAs (all co-resident)
#define RPC     16           // rows per CTA
#define NTHR    1024         // 32 warps: 2 warps per row
#define XBLK    32           // x staging window (steps)

// ---------------- device scratch ----------------
__device__ __half    g_state[2][R_ * B_];     // fp16 state, [r][b], 64B/row
__device__ float     g_final[R_ * B_];        // fp32 final state for outproj
__device__ unsigned  g_cols[R_][CAP];         // col * 8 (uint2 offset of fp16 row)
__device__ float     g_vals[R_][CAP];
__device__ int       g_cnt[R_];               // padded to multiple of 16, >=16
__device__ unsigned  g_flag[GRID * 32];       // one 128B line per CTA

// ---------------- helpers ----------------
__device__ __forceinline__ unsigned ld_acq(const unsigned* p) {
    unsigned v;
    asm volatile("ld.acquire.gpu.u32 %0, [%1];" : "=r"(v) : "l"(p) : "memory");
    return v;
}
__device__ __forceinline__ void st_rel(unsigned* p, unsigned v) {
    asm volatile("st.release.gpu.u32 [%0], %1;" :: "l"(p), "r"(v) : "memory");
}
__device__ __forceinline__ float tanh_fast(float x) {
    float y;
    asm("tanh.approx.f32 %0, %1;" : "=f"(y) : "f"(x));
    return y;
}

// ---------------- P1: sparse compaction + init ----------------
__global__ void prep_kernel(const float* __restrict__ W) {
    int r = blockIdx.x;
    int lane = threadIdx.x;
    const float* row = W + (size_t)r * R_;

    int base = 0;
    for (int c0 = 0; c0 < R_; c0 += 32) {
        float v = row[c0 + lane];
        unsigned m = __ballot_sync(0xffffffffu, v != 0.0f);
        if (v != 0.0f) {
            int off = __popc(m & ((1u << lane) - 1u));
            int p = base + off;
            if (p < CAP) {
                g_cols[r][p] = (unsigned)(c0 + lane) * 8u;   // uint2 units per fp16 row
                g_vals[r][p] = v;
            }
        }
        base += __popc(m);
    }
    if (base > CAP) base = CAP;
    int padded = (base + 15) & ~15;
    if (padded < 16) padded = 16;
    if (padded > CAP) padded = CAP;
    for (int p = base + lane; p < padded; p += 32) {
        g_cols[r][p] = ((unsigned)(r * 7 + p * 13) & (R_ - 1)) * 8u;
        g_vals[r][p] = 0.0f;
    }
    if (lane == 0) g_cnt[r] = padded;

    // reset per-launch mutable state (graph replay safe)
    g_state[0][r * B_ + lane] = __float2half(0.0f);
    if (r < GRID && lane == 0) g_flag[r << 5] = 0u;
}

// ---------------- P2: persistent recurrence (2 warps per row) ----------------
__global__ void __launch_bounds__(NTHR, 1)
esn_kernel(const float* __restrict__ x,        // [B,T,I]
           const float* __restrict__ win,      // [R,I]
           const float* __restrict__ noise,    // [B,R]
           float* __restrict__ states_out) {   // [B,T,R]
    __shared__ uint2 snnz[RPC][CAP];           // (col*8, val bits)  20 KB
    __shared__ float part[RPC][B_ + 1];        // h=1 partial sums, 2.1 KB
    __shared__ float tile[RPC][B_ + 1];        // staged fp32 outputs, 2.1 KB
    __shared__ float xs[XBLK][B_][4];          // 32-step x window, 16 KB

    const int tid  = threadIdx.x;
    const int w    = tid >> 6;                 // row (0..15): 2 warps per row
    const int h    = (tid >> 5) & 1;           // warp half: nnz-quad range selector
    const int lane = tid & 31;
    const int q    = lane >> 3;                // quarter: handles nnz 4j+q
    const int l    = lane & 7;                 // batch quad: batches 4l..4l+3
    const int rbase = blockIdx.x * RPC;
    const int r = rbase + w;

    // preload sparse row into SMEM (both warps of the row cooperate)
    const int cnt = g_cnt[r];
    for (int k = (h << 5) + lane; k < cnt; k += 64)
        snnz[w][k] = make_uint2(g_cols[r][k], __float_as_uint(g_vals[r][k]));

    // per-thread constants (only h=0, q=0 lanes use them)
    float nz[4];
    #pragma unroll
    for (int i = 0; i < 4; i++) nz[i] = noise[(size_t)(4 * l + i) * R_ + r];
    const float w0 = win[r * 3 + 0];
    const float w1 = win[r * 3 + 1];
    const float w2 = win[r * 3 + 2];

    auto refill_x = [&](int t0) {
        for (int g = tid; g < XBLK * B_ * I_; g += NTHR) {
            int b = g / (XBLK * I_);
            int rem = g - b * (XBLK * I_);
            int tp = rem / I_, i = rem - tp * I_;
            float v = (t0 + tp < T_) ? __ldg(&x[(size_t)b * (T_ * I_) + (t0 + tp) * I_ + i])
                                     : 0.0f;
            xs[tp][b][i] = v;
        }
    };
    refill_x(0);
    __syncthreads();

    // quad ranges per warp: nj quads total (multiple of 4); split into two mult-of-4 halves
    const int nj  = cnt >> 2;
    int njA = ((nj >> 1) + 3) & ~3;
    if (njA > nj) njA = nj;
    const int jb = h ? njA : 0;
    const int je = h ? nj  : njA;

    for (int t = 0; t < T_; t++) {
        const uint2* cur = (const uint2*)&g_state[t & 1][0];
        uint2* nxt       = (uint2*)&g_state[(t + 1) & 1][0];
        const int tw = t & (XBLK - 1);

        float acc[4];
        if (h == 0) {
            #pragma unroll
            for (int i = 0; i < 4; i++) {
                int b = 4 * l + i;
                float ax = fmaf(w0, xs[tw][b][0],
                           fmaf(w1, xs[tw][b][1],
                           fmaf(w2, xs[tw][b][2], nz[i])));
                acc[i] = (q == 0) ? ax : 0.0f;
            }
        } else {
            #pragma unroll
            for (int i = 0; i < 4; i++) acc[i] = 0.0f;
        }

        // ---- pipelined quad gather over [jb, je): LDG.64 = 4 nnz per load ----
        {
            uint2 sA[4]; float vA[4];
            uint2 sB[4]; float vB[4];

            auto load4 = [&](uint2* s, float* v, int jbase) {
                #pragma unroll
                for (int jj = 0; jj < 4; jj++) {
                    uint2 e = snnz[w][((jbase + jj) << 2) + q];
                    v[jj] = __uint_as_float(e.y);
                    s[jj] = __ldcg(cur + e.x + l);     // 8B = 4 fp16 batches
                }
            };
            auto consume4 = [&](const uint2* s, const float* v) {
                #pragma unroll
                for (int jj = 0; jj < 4; jj++) {
                    float2 f0 = __half22float2(*(const __half2*)&s[jj].x);
                    float2 f1 = __half22float2(*(const __half2*)&s[jj].y);
                    acc[0] = fmaf(v[jj], f0.x, acc[0]);
                    acc[1] = fmaf(v[jj], f0.y, acc[1]);
                    acc[2] = fmaf(v[jj], f1.x, acc[2]);
                    acc[3] = fmaf(v[jj], f1.y, acc[3]);
                }
            };

            const int nq = je - jb;
            if (nq > 0) {
                load4(sA, vA, jb);
                for (int j = jb + 4; j < je; j += 8) {
                    load4(sB, vB, j);
                    consume4(sA, vA);
                    if (j + 4 < je) load4(sA, vA, j + 4);
                    consume4(sB, vB);
                }
                if ((nq >> 2) & 1) consume4(sA, vA);
            }
        }

        // merge quarters within the warp
        #pragma unroll
        for (int i = 0; i < 4; i++) {
            acc[i] += __shfl_xor_sync(0xffffffffu, acc[i], 8);
            acc[i] += __shfl_xor_sync(0xffffffffu, acc[i], 16);
        }

        // merge warp halves through SMEM
        if (h == 1 && q == 0) {
            #pragma unroll
            for (int i = 0; i < 4; i++) part[w][4 * l + i] = acc[i];
        }
        __syncthreads();

        if (h == 0 && q == 0) {
            #pragma unroll
            for (int i = 0; i < 4; i++)
                acc[i] = tanh_fast(acc[i] + part[w][4 * l + i]);

            __half2 h0 = __floats2half2_rn(acc[0], acc[1]);
            __half2 h1 = __floats2half2_rn(acc[2], acc[3]);
            uint2 pk = make_uint2(*(unsigned*)&h0, *(unsigned*)&h1);
            nxt[r * 8 + l] = pk;                  // 64B coalesced state store
            tile[w][4 * l + 0] = acc[0];
            tile[w][4 * l + 1] = acc[1];
            tile[w][4 * l + 2] = acc[2];
            tile[w][4 * l + 3] = acc[3];
            if (t == T_ - 1) {
                #pragma unroll
                for (int i = 0; i < 4; i++)
                    g_final[r * B_ + 4 * l + i] = acc[i];
            }
        }
        __syncthreads();                          // all state/tile stores done

        // arrival: release orders all prior stores (cumulative via bar.sync)
        if (tid == 0) st_rel(&g_flag[blockIdx.x << 5], (unsigned)(t + 1));

        // ---- off-critical-path work while barrier resolves ----
        if (h == 0) {   // transposed states write: 64B per half-warp
            int b  = w + ((lane >> 4) << 4);      // w or w+16
            int rr = lane & 15;
            __stcs(&states_out[(size_t)b * (T_ * R_) + (size_t)t * R_ + rbase + rr],
                   tile[rr][b]);
        }
        if (((t + 1) & (XBLK - 1)) == 0 && t + 1 < T_)
            refill_x(t + 1);                      // next 32-step x window

        // ---- flat barrier: 128 threads poll 128 distinct flag lines ----
        if (tid < GRID) {
            while (ld_acq(&g_flag[tid << 5]) < (unsigned)(t + 1)) { }
        }
        __syncthreads();
    }
}

// ---------------- P3: output projection ----------------
__global__ void outproj_kernel(const float* __restrict__ wout,  // [O,R]
                               float* __restrict__ out) {       // [B*O]
    __shared__ float red[256];
    int pair = blockIdx.x;            // 0..95
    int b = pair / O_, o = pair - b * O_;

    float sum = 0.0f;
    for (int r = threadIdx.x; r < R_; r += blockDim.x)
        sum += g_final[r * B_ + b] * wout[o * R_ + r];

    red[threadIdx.x] = sum;
    __syncthreads();
    for (int s = 128; s > 0; s >>= 1) {
        if (threadIdx.x < s) red[threadIdx.x] += red[threadIdx.x + s];
        __syncthreads();
    }
    if (threadIdx.x == 0) out[b * O_ + o] = red[0];
}

// ---------------- launch ----------------
extern "C" void kernel_launch(void* const* d_in, const int* in_sizes, int n_in,
                              void* d_out, int out_size) {
    (void)in_sizes; (void)n_in; (void)out_size;
    const float* x     = (const float*)d_in[0];   // [B,T,I]
    const float* win   = (const float*)d_in[1];   // [R,I]
    const float* wres  = (const float*)d_in[2];   // [R,R]
    const float* wout  = (const float*)d_in[3];   // [O,R]
    const float* noise = (const float*)d_in[4];   // [B,R]
    float* out = (float*)d_out;                   // [B*O] then [B,T,R]

    prep_kernel<<<R_, 32>>>(wres);
    esn_kernel<<<GRID, NTHR>>>(x, win, noise, out + B_ * O_);
    outproj_kernel<<<B_ * O_, 256>>>(wout, out);
}

// round 14
// speedup vs baseline: 1.9477x; 1.1396x over previous
#include <cuda_runtime.h>
#include <cuda_fp16.h>
#include <cstdint>

// Problem constants
#define B_  32
#define T_  1000
#define I_  3
#define R_  2048
#define O_  3

#define CAP     160          // per-row nnz capacity (padded to mult of 16)
#define GRID    128          // persistent CTAs (all co-resident)
#define RPC     16           // rows per CTA
#define NTHR    512          // 16 warps, warp-per-row

// ---------------- device scratch ----------------
__device__ __half            g_state[2][R_ * B_];     // fp16 state, [r][b], 64B/row
__device__ float             g_final[R_ * B_];        // fp32 final state for outproj
__device__ unsigned          g_cols[R_][CAP];         // col * 16 (uint-word offset of fp16 row)
__device__ float             g_vals[R_][CAP];
__device__ int               g_cnt[R_];               // padded to multiple of 16, >=16
__device__ volatile unsigned g_flag[GRID * 32];       // one 128B line per CTA

// ---------------- helpers ----------------
__device__ __forceinline__ unsigned ld_acq(const volatile unsigned* p) {
    unsigned v;
    asm volatile("ld.acquire.gpu.u32 %0, [%1];" : "=r"(v) : "l"((const unsigned*)p) : "memory");
    return v;
}
__device__ __forceinline__ void st_rel(volatile unsigned* p, unsigned v) {
    asm volatile("st.release.gpu.u32 [%0], %1;" :: "l"((unsigned*)p), "r"(v) : "memory");
}
__device__ __forceinline__ float tanh_fast(float x) {
    float y;
    asm("tanh.approx.f32 %0, %1;" : "=f"(y) : "f"(x));
    return y;
}

// ---------------- P1: sparse compaction + init ----------------
__global__ void prep_kernel(const float* __restrict__ W) {
    int r = blockIdx.x;
    int lane = threadIdx.x;
    const float* row = W + (size_t)r * R_;

    int base = 0;
    for (int c0 = 0; c0 < R_; c0 += 32) {
        float v = row[c0 + lane];
        unsigned m = __ballot_sync(0xffffffffu, v != 0.0f);
        if (v != 0.0f) {
            int off = __popc(m & ((1u << lane) - 1u));
            int p = base + off;
            if (p < CAP) {
                g_cols[r][p] = (unsigned)(c0 + lane) * 16u;   // uint words per fp16 row
                g_vals[r][p] = v;
            }
        }
        base += __popc(m);
    }
    if (base > CAP) base = CAP;
    int padded = (base + 15) & ~15;
    if (padded < 16) padded = 16;
    if (padded > CAP) padded = CAP;
    for (int p = base + lane; p < padded; p += 32) {
        g_cols[r][p] = ((unsigned)(r * 7 + p * 13) & (R_ - 1)) * 16u;
        g_vals[r][p] = 0.0f;
    }
    if (lane == 0) g_cnt[r] = padded;

    // reset per-launch mutable state (graph replay safe)
    g_state[0][r * B_ + lane] = __float2half(0.0f);
    if (r < GRID && lane == 0) g_flag[r << 5] = 0u;
}

// ---------------- P2: persistent recurrence ----------------
__global__ void __launch_bounds__(NTHR, 1)
esn_kernel(const float* __restrict__ x,        // [B,T,I]
           const float* __restrict__ win,      // [R,I]
           const float* __restrict__ noise,    // [B,R]
           float* __restrict__ states_out) {   // [B,T,R]
    __shared__ uint2 snnz[RPC][CAP];           // (col*16, val bits)  20 KB
    __shared__ float tile[RPC][B_ + 1];        // staged fp32 outputs for transpose
    __shared__ float xs[B_][4];                // x_t per batch

    const int tid  = threadIdx.x;
    const int w    = tid >> 5;                 // warp = local row
    const int lane = tid & 31;
    const int hsel = lane >> 4;                // 0: even nnz, 1: odd nnz
    const int hl   = lane & 15;                // half-lane -> batch pair (2hl, 2hl+1)
    const int b0   = hl << 1;
    const int b1   = b0 + 1;
    const int rbase = blockIdx.x * RPC;
    const int r = rbase + w;

    // preload sparse row into SMEM (reused for all 1000 steps)
    const int cnt = g_cnt[r];
    for (int k = lane; k < cnt; k += 32)
        snnz[w][k] = make_uint2(g_cols[r][k], __float_as_uint(g_vals[r][k]));

    // per-thread constants (2 batches per thread)
    const float nz0 = noise[(size_t)b0 * R_ + r];
    const float nz1 = noise[(size_t)b1 * R_ + r];
    const float w0 = win[r * 3 + 0];
    const float w1 = win[r * 3 + 1];
    const float w2 = win[r * 3 + 2];

    // stage x for t=0
    if (tid < B_ * I_) {
        int b = tid / 3, i = tid - b * 3;
        xs[b][i] = x[(size_t)b * (T_ * I_) + i];
    }
    __syncthreads();

    const int npairs = cnt >> 1;               // LDG pairs per row (multiple of 8)

    for (int t = 0; t < T_; t++) {
        const unsigned* cur = (const unsigned*)&g_state[t & 1][0];
        __half2* nxt        = (__half2*)&g_state[(t + 1) & 1][0];

        float ax = fmaf(w0, xs[b0][0], fmaf(w1, xs[b0][1], fmaf(w2, xs[b0][2], nz0)));
        float ay = fmaf(w0, xs[b1][0], fmaf(w1, xs[b1][1], fmaf(w2, xs[b1][2], nz1)));
        // split across even/odd halves: recurrent accum starts at 0 on odd half
        float accx = (hsel == 0) ? ax : 0.0f;
        float accy = (hsel == 0) ? ay : 0.0f;

        // ---- software-pipelined gather: 8 LDGs/chunk, each LDG covers 2 nnz ----
        unsigned sA[8]; float vA[8];
        unsigned sB[8]; float vB[8];

        auto load8 = [&](unsigned* s, float* v, int pbase) {
            #pragma unroll
            for (int j = 0; j < 8; j++) {
                uint2 e = snnz[w][((pbase + j) << 1) + hsel];
                v[j] = __uint_as_float(e.y);
                s[j] = __ldcg(cur + e.x + hl);     // L2-only, 4B = 2 fp16 batches
            }
        };
        auto consume8 = [&](const unsigned* s, const float* v) {
            #pragma unroll
            for (int j = 0; j < 8; j++) {
                float2 f = __half22float2(*(const __half2*)&s[j]);
                accx = fmaf(v[j], f.x, accx);
                accy = fmaf(v[j], f.y, accy);
            }
        };

        load8(sA, vA, 0);
        for (int p = 8; p < npairs; p += 16) {
            load8(sB, vB, p);
            consume8(sA, vA);
            if (p + 8 < npairs) load8(sA, vA, p + 8);
            consume8(sB, vB);
        }
        if ((npairs >> 3) & 1) consume8(sA, vA);

        // merge even/odd halves (lanes L and L+16 hold partials for same batches)
        accx += __shfl_xor_sync(0xffffffffu, accx, 16);
        accy += __shfl_xor_sync(0xffffffffu, accy, 16);

        float sv = tanh_fast(hsel == 0 ? accx : accy);
        float sp = __shfl_xor_sync(0xffffffffu, sv, 16);   // partner's value

        if (hsel == 0) {
            nxt[r * (B_ / 2) + hl] = __floats2half2_rn(sv, sp);   // 64B coalesced
            tile[w][b0] = sv;
            tile[w][b1] = sp;
            if (t == T_ - 1) {
                g_final[r * B_ + b0] = sv;
                g_final[r * B_ + b1] = sp;
            }
        }
        __syncthreads();                         // all state/tile stores done

        // ---- arrival: release store orders all prior stores (bar.sync cumulative)
        if (tid == 0) st_rel(&g_flag[blockIdx.x << 5], (unsigned)(t + 1));

        // ---- off-critical-path work while others arrive ----
        {   // transposed states write: half-warp writes 64B contiguous per batch
            int b  = w + ((lane >> 4) << 4);     // w or w+16
            int rr = lane & 15;
            states_out[(size_t)b * (T_ * R_) + (size_t)t * R_ + rbase + rr] = tile[rr][b];
        }
        if (t + 1 < T_ && tid < B_ * I_) {       // stage x for t+1
            int b = tid / 3, i = tid - b * 3;
            xs[b][i] = x[(size_t)b * (T_ * I_) + (t + 1) * I_ + i];
        }

        // ---- wait: 128 threads poll 128 distinct flag lines (acquire per read) ----
        if (tid < GRID) {
            while (ld_acq(&g_flag[tid << 5]) < (unsigned)(t + 1)) { }
        }
        __syncthreads();
    }
}

// ---------------- P3: output projection ----------------
__global__ void outproj_kernel(const float* __restrict__ wout,  // [O,R]
                               float* __restrict__ out) {       // [B*O]
    __shared__ float red[256];
    int pair = blockIdx.x;            // 0..95
    int b = pair / O_, o = pair - b * O_;

    float sum = 0.0f;
    for (int r = threadIdx.x; r < R_; r += blockDim.x)
        sum += g_final[r * B_ + b] * wout[o * R_ + r];

    red[threadIdx.x] = sum;
    __syncthreads();
    for (int s = 128; s > 0; s >>= 1) {
        if (threadIdx.x < s) red[threadIdx.x] += red[threadIdx.x + s];
        __syncthreads();
    }
    if (threadIdx.x == 0) out[b * O_ + o] = red[0];
}

// ---------------- launch ----------------
extern "C" void kernel_launch(void* const* d_in, const int* in_sizes, int n_in,
                              void* d_out, int out_size) {
    (void)in_sizes; (void)n_in; (void)out_size;
    const float* x     = (const float*)d_in[0];   // [B,T,I]
    const float* win   = (const float*)d_in[1];   // [R,I]
    const float* wres  = (const float*)d_in[2];   // [R,R]
    const float* wout  = (const float*)d_in[3];   // [O,R]
    const float* noise = (const float*)d_in[4];   // [B,R]
    float* out = (float*)d_out;                   // [B*O] then [B,T,R]

    prep_kernel<<<R_, 32>>>(wres);
    esn_kernel<<<GRID, NTHR>>>(x, win, noise, out + B_ * O_);
    outproj_kernel<<<B_ * O_, 256>>>(wout, out);
}